// round 2
// baseline (speedup 1.0000x reference)
#include <cuda_runtime.h>

// Problem constants
#define T_SEQ   4096
#define D_MODEL 1024
#define N_HQ    16
#define N_HKV   4
#define HD      64
#define DKV     256     // N_HKV * HD
#define SCALE   0.125f  // 1/sqrt(64)

// Scratch (static device globals — allocation-free per harness rules)
__device__ float g_Q[T_SEQ * D_MODEL];
__device__ float g_K[T_SEQ * DKV];
__device__ float g_V[T_SEQ * DKV];
__device__ float g_C[T_SEQ * D_MODEL];

// ---------------------------------------------------------------------------
// Tiled SGEMM: C[M,N] = A[M,K] @ B[K,N], all row-major, fp32.
// BM=BN=128, BK=8, 256 threads, 8x8 per-thread microtile.
// All problem dims divide the tile sizes (4096,1024,256 % 128 == 0; K % 8 == 0)
// so no bounds checks.
// ---------------------------------------------------------------------------
#define BM 128
#define BN 128
#define BK 8
__global__ void __launch_bounds__(256)
sgemm_kernel(const float* __restrict__ A, const float* __restrict__ B,
             float* __restrict__ C, int M, int N, int K)
{
    __shared__ float As[BK][BM];   // A tile stored transposed
    __shared__ float Bs[BK][BN];

    const int tid = threadIdx.x;
    const int bx  = blockIdx.x;    // N direction
    const int by  = blockIdx.y;    // M direction

    const int tx = tid & 15;       // 16 threads in N
    const int ty = tid >> 4;       // 16 threads in M

    // A-tile load mapping: 128 rows x 8 cols = 256 float4 (one per thread)
    const int arow  = tid >> 1;
    const int acol4 = (tid & 1) * 4;
    // B-tile load mapping: 8 rows x 128 cols = 256 float4
    const int brow  = tid >> 5;
    const int bcol4 = (tid & 31) * 4;

    const float* Ab = A + (long)(by * BM) * K;
    const float* Bb = B + bx * BN;

    float acc[8][8];
#pragma unroll
    for (int i = 0; i < 8; i++)
#pragma unroll
        for (int j = 0; j < 8; j++) acc[i][j] = 0.f;

    for (int k0 = 0; k0 < K; k0 += BK) {
        // load A tile (transposed into As)
        float4 a = *(const float4*)&Ab[(long)arow * K + k0 + acol4];
        As[acol4 + 0][arow] = a.x;
        As[acol4 + 1][arow] = a.y;
        As[acol4 + 2][arow] = a.z;
        As[acol4 + 3][arow] = a.w;
        // load B tile
        *(float4*)&Bs[brow][bcol4] =
            *(const float4*)&Bb[(long)(k0 + brow) * N + bcol4];
        __syncthreads();

        float ra[8], rb[8];
#pragma unroll
        for (int kk = 0; kk < BK; kk++) {
#pragma unroll
            for (int i = 0; i < 8; i++) ra[i] = As[kk][ty * 8 + i];
#pragma unroll
            for (int j = 0; j < 8; j++) rb[j] = Bs[kk][tx * 8 + j];
#pragma unroll
            for (int i = 0; i < 8; i++)
#pragma unroll
                for (int j = 0; j < 8; j++)
                    acc[i][j] += ra[i] * rb[j];
        }
        __syncthreads();
    }

    float* Cb = C + (long)(by * BM + ty * 8) * N + bx * BN + tx * 8;
#pragma unroll
    for (int i = 0; i < 8; i++) {
        float4 c0 = make_float4(acc[i][0], acc[i][1], acc[i][2], acc[i][3]);
        float4 c1 = make_float4(acc[i][4], acc[i][5], acc[i][6], acc[i][7]);
        *(float4*)&Cb[(long)i * N + 0] = c0;
        *(float4*)&Cb[(long)i * N + 4] = c1;
    }
}

// ---------------------------------------------------------------------------
// Flash attention (fp32, causal, GQA): one CTA = one head x 128 q-rows.
// One thread per q-row: q and o accumulators in registers (64 each),
// K/V tiles of 64 rows in smem (broadcast reads), per-row scores staged in
// padded smem (thread-private rows, no cross-thread hazard).
// ---------------------------------------------------------------------------
#define AQ 128   // q rows per block == threads per block
#define AK 64    // k rows per tile

__global__ void __launch_bounds__(AQ)
attn_kernel(const float* __restrict__ Q, const float* __restrict__ K,
            const float* __restrict__ V, float* __restrict__ O)
{
    extern __shared__ float sm[];
    float (*Ks)[HD]     = (float(*)[HD])sm;                 // [AK][64]
    float (*Vs)[HD]     = (float(*)[HD])(sm + AK * HD);     // [AK][64]
    float (*Ss)[AK + 1] = (float(*)[AK + 1])(sm + 2 * AK * HD); // [AQ][65]

    const int h    = blockIdx.y;         // q head
    const int kv   = h >> 2;             // kv head = h / G, G = 4
    const int r    = threadIdx.x;        // 0..127
    const int qrow = blockIdx.x * AQ + r;

    const float* qptr = Q + (long)qrow * D_MODEL + h * HD;

    float q[HD], o[HD];
#pragma unroll
    for (int d = 0; d < HD; d++) { q[d] = qptr[d] * SCALE; o[d] = 0.f; }

    float m = -3.0e38f;
    float l = 0.f;

    const int kend = blockIdx.x * AQ + AQ;   // exclusive causal bound for tile

    for (int k0 = 0; k0 < kend; k0 += AK) {
        __syncthreads();   // protect Ks/Vs from previous iteration's readers
        // cooperative load: 64 rows x 16 float4 per tensor, 128 threads
#pragma unroll
        for (int i = r; i < AK * 16; i += AQ) {
            int row = i >> 4;
            int c4  = (i & 15) * 4;
            long gro = (long)(k0 + row) * DKV + kv * HD + c4;
            *(float4*)&Ks[row][c4] = *(const float4*)&K[gro];
            *(float4*)&Vs[row][c4] = *(const float4*)&V[gro];
        }
        __syncthreads();

        // causal: this row only sees k <= qrow
        int jmax = qrow - k0 + 1;
        if (jmax > AK) jmax = AK;
        if (jmax <= 0) continue;   // fully-masked tile for this row

        // pass 1: scores + tile max
        float mt = m;
        for (int j = 0; j < jmax; j++) {
            float s = 0.f;
#pragma unroll
            for (int d = 0; d < HD; d++) s += q[d] * Ks[j][d];
            Ss[r][j] = s;
            mt = fmaxf(mt, s);
        }

        const float corr = __expf(m - mt);
        l *= corr;
#pragma unroll
        for (int d = 0; d < HD; d++) o[d] *= corr;

        // pass 2: exp + PV accumulate
        float lt = 0.f;
        for (int j = 0; j < jmax; j++) {
            float p = __expf(Ss[r][j] - mt);
            lt += p;
#pragma unroll
            for (int d = 0; d < HD; d++) o[d] += p * Vs[j][d];
        }
        l += lt;
        m = mt;
    }

    const float inv = 1.f / l;
    float* optr = O + (long)qrow * D_MODEL + h * HD;
#pragma unroll
    for (int d = 0; d < HD; d += 4) {
        float4 v = make_float4(o[d] * inv, o[d + 1] * inv,
                               o[d + 2] * inv, o[d + 3] * inv);
        *(float4*)&optr[d] = v;
    }
}

// ---------------------------------------------------------------------------
// Launch
// ---------------------------------------------------------------------------
extern "C" void kernel_launch(void* const* d_in, const int* in_sizes, int n_in,
                              void* d_out, int out_size)
{
    const float* x  = (const float*)d_in[0];
    const float* Wq = (const float*)d_in[1];
    const float* Wk = (const float*)d_in[2];
    const float* Wv = (const float*)d_in[3];
    const float* Wo = (const float*)d_in[4];
    float* out = (float*)d_out;

    float *Q, *K, *V, *C;
    cudaGetSymbolAddress((void**)&Q, g_Q);
    cudaGetSymbolAddress((void**)&K, g_K);
    cudaGetSymbolAddress((void**)&V, g_V);
    cudaGetSymbolAddress((void**)&C, g_C);

    const int attn_smem = (2 * AK * HD + AQ * (AK + 1)) * (int)sizeof(float); // 66048 B
    static bool configured = false;
    if (!configured) {
        cudaFuncSetAttribute(attn_kernel,
                             cudaFuncAttributeMaxDynamicSharedMemorySize,
                             attn_smem);
        configured = true;
    }

    // Projections
    sgemm_kernel<<<dim3(D_MODEL / BN, T_SEQ / BM), 256>>>(x, Wq, Q, T_SEQ, D_MODEL, D_MODEL);
    sgemm_kernel<<<dim3(DKV / BN,     T_SEQ / BM), 256>>>(x, Wk, K, T_SEQ, DKV,     D_MODEL);
    sgemm_kernel<<<dim3(DKV / BN,     T_SEQ / BM), 256>>>(x, Wv, V, T_SEQ, DKV,     D_MODEL);

    // Attention
    attn_kernel<<<dim3(T_SEQ / AQ, N_HQ), AQ, attn_smem>>>(Q, K, V, C);

    // Output projection
    sgemm_kernel<<<dim3(D_MODEL / BN, T_SEQ / BM), 256>>>(C, Wo, out, T_SEQ, D_MODEL, D_MODEL);
}

// round 3
// speedup vs baseline: 1.0117x; 1.0117x over previous
#include <cuda_runtime.h>

// Problem constants
#define T_SEQ   4096
#define D_MODEL 1024
#define N_HQ    16
#define N_HKV   4
#define HD      64
#define DKV     256     // N_HKV * HD
#define SCALE   0.125f  // 1/sqrt(64)

// Scratch (static device globals — allocation-free per harness rules)
__device__ float g_Q[T_SEQ * D_MODEL];
__device__ float g_K[T_SEQ * DKV];
__device__ float g_V[T_SEQ * DKV];
__device__ float g_C[T_SEQ * D_MODEL];

// ---------------------------------------------------------------------------
// Tiled SGEMM: C[M,N] = A[M,K] @ B[K,N], all row-major, fp32.
// BM=BN=128, BK=8, 256 threads, 8x8 per-thread microtile.
// All problem dims divide the tile sizes (4096,1024,256 % 128 == 0; K % 8 == 0)
// so no bounds checks.
// ---------------------------------------------------------------------------
#define BM 128
#define BN 128
#define BK 8
__global__ void __launch_bounds__(256)
sgemm_kernel(const float* __restrict__ A, const float* __restrict__ B,
             float* __restrict__ C, int M, int N, int K)
{
    __shared__ float As[BK][BM];   // A tile stored transposed
    __shared__ float Bs[BK][BN];

    const int tid = threadIdx.x;
    const int bx  = blockIdx.x;    // N direction
    const int by  = blockIdx.y;    // M direction

    const int tx = tid & 15;       // 16 threads in N
    const int ty = tid >> 4;       // 16 threads in M

    // A-tile load mapping: 128 rows x 8 cols = 256 float4 (one per thread)
    const int arow  = tid >> 1;
    const int acol4 = (tid & 1) * 4;
    // B-tile load mapping: 8 rows x 128 cols = 256 float4
    const int brow  = tid >> 5;
    const int bcol4 = (tid & 31) * 4;

    const float* Ab = A + (long)(by * BM) * K;
    const float* Bb = B + bx * BN;

    float acc[8][8];
#pragma unroll
    for (int i = 0; i < 8; i++)
#pragma unroll
        for (int j = 0; j < 8; j++) acc[i][j] = 0.f;

    for (int k0 = 0; k0 < K; k0 += BK) {
        // load A tile (transposed into As)
        float4 a = *(const float4*)&Ab[(long)arow * K + k0 + acol4];
        As[acol4 + 0][arow] = a.x;
        As[acol4 + 1][arow] = a.y;
        As[acol4 + 2][arow] = a.z;
        As[acol4 + 3][arow] = a.w;
        // load B tile
        *(float4*)&Bs[brow][bcol4] =
            *(const float4*)&Bb[(long)(k0 + brow) * N + bcol4];
        __syncthreads();

        float ra[8], rb[8];
#pragma unroll
        for (int kk = 0; kk < BK; kk++) {
#pragma unroll
            for (int i = 0; i < 8; i++) ra[i] = As[kk][ty * 8 + i];
#pragma unroll
            for (int j = 0; j < 8; j++) rb[j] = Bs[kk][tx * 8 + j];
#pragma unroll
            for (int i = 0; i < 8; i++)
#pragma unroll
                for (int j = 0; j < 8; j++)
                    acc[i][j] += ra[i] * rb[j];
        }
        __syncthreads();
    }

    float* Cb = C + (long)(by * BM + ty * 8) * N + bx * BN + tx * 8;
#pragma unroll
    for (int i = 0; i < 8; i++) {
        float4 c0 = make_float4(acc[i][0], acc[i][1], acc[i][2], acc[i][3]);
        float4 c1 = make_float4(acc[i][4], acc[i][5], acc[i][6], acc[i][7]);
        *(float4*)&Cb[(long)i * N + 0] = c0;
        *(float4*)&Cb[(long)i * N + 4] = c1;
    }
}

// ---------------------------------------------------------------------------
// Flash attention (fp32, causal, GQA): one CTA = one head x 128 q-rows.
// One thread per q-row: q and o accumulators in registers (64 each),
// K/V tiles of 64 rows in smem (broadcast reads), per-row scores staged in
// padded smem (thread-private rows, no cross-thread hazard).
// ---------------------------------------------------------------------------
#define AQ 128   // q rows per block == threads per block
#define AK 64    // k rows per tile

__global__ void __launch_bounds__(AQ)
attn_kernel(const float* __restrict__ Q, const float* __restrict__ K,
            const float* __restrict__ V, float* __restrict__ O)
{
    extern __shared__ float sm[];
    float (*Ks)[HD]     = (float(*)[HD])sm;                 // [AK][64]
    float (*Vs)[HD]     = (float(*)[HD])(sm + AK * HD);     // [AK][64]
    float (*Ss)[AK + 1] = (float(*)[AK + 1])(sm + 2 * AK * HD); // [AQ][65]

    const int h    = blockIdx.y;         // q head
    const int kv   = h >> 2;             // kv head = h / G, G = 4
    const int r    = threadIdx.x;        // 0..127
    const int qrow = blockIdx.x * AQ + r;

    const float* qptr = Q + (long)qrow * D_MODEL + h * HD;

    float q[HD], o[HD];
#pragma unroll
    for (int d = 0; d < HD; d++) { q[d] = qptr[d] * SCALE; o[d] = 0.f; }

    float m = -3.0e38f;
    float l = 0.f;

    const int kend = blockIdx.x * AQ + AQ;   // exclusive causal bound for tile

    for (int k0 = 0; k0 < kend; k0 += AK) {
        __syncthreads();   // protect Ks/Vs from previous iteration's readers
        // cooperative load: 64 rows x 16 float4 per tensor, 128 threads
#pragma unroll
        for (int i = r; i < AK * 16; i += AQ) {
            int row = i >> 4;
            int c4  = (i & 15) * 4;
            long gro = (long)(k0 + row) * DKV + kv * HD + c4;
            *(float4*)&Ks[row][c4] = *(const float4*)&K[gro];
            *(float4*)&Vs[row][c4] = *(const float4*)&V[gro];
        }
        __syncthreads();

        // causal: this row only sees k <= qrow
        int jmax = qrow - k0 + 1;
        if (jmax > AK) jmax = AK;
        if (jmax <= 0) continue;   // fully-masked tile for this row

        // pass 1: scores + tile max
        float mt = m;
        for (int j = 0; j < jmax; j++) {
            float s = 0.f;
#pragma unroll
            for (int d = 0; d < HD; d++) s += q[d] * Ks[j][d];
            Ss[r][j] = s;
            mt = fmaxf(mt, s);
        }

        const float corr = __expf(m - mt);
        l *= corr;
#pragma unroll
        for (int d = 0; d < HD; d++) o[d] *= corr;

        // pass 2: exp + PV accumulate
        float lt = 0.f;
        for (int j = 0; j < jmax; j++) {
            float p = __expf(Ss[r][j] - mt);
            lt += p;
#pragma unroll
            for (int d = 0; d < HD; d++) o[d] += p * Vs[j][d];
        }
        l += lt;
        m = mt;
    }

    const float inv = 1.f / l;
    float* optr = O + (long)qrow * D_MODEL + h * HD;
#pragma unroll
    for (int d = 0; d < HD; d += 4) {
        float4 v = make_float4(o[d] * inv, o[d + 1] * inv,
                               o[d + 2] * inv, o[d + 3] * inv);
        *(float4*)&optr[d] = v;
    }
}

// ---------------------------------------------------------------------------
// Launch
// ---------------------------------------------------------------------------
extern "C" void kernel_launch(void* const* d_in, const int* in_sizes, int n_in,
                              void* d_out, int out_size)
{
    const float* x  = (const float*)d_in[0];
    const float* Wq = (const float*)d_in[1];
    const float* Wk = (const float*)d_in[2];
    const float* Wv = (const float*)d_in[3];
    const float* Wo = (const float*)d_in[4];
    float* out = (float*)d_out;

    float *Q, *K, *V, *C;
    cudaGetSymbolAddress((void**)&Q, g_Q);
    cudaGetSymbolAddress((void**)&K, g_K);
    cudaGetSymbolAddress((void**)&V, g_V);
    cudaGetSymbolAddress((void**)&C, g_C);

    const int attn_smem = (2 * AK * HD + AQ * (AK + 1)) * (int)sizeof(float); // 66048 B
    static bool configured = false;
    if (!configured) {
        cudaFuncSetAttribute(attn_kernel,
                             cudaFuncAttributeMaxDynamicSharedMemorySize,
                             attn_smem);
        configured = true;
    }

    // Projections
    sgemm_kernel<<<dim3(D_MODEL / BN, T_SEQ / BM), 256>>>(x, Wq, Q, T_SEQ, D_MODEL, D_MODEL);
    sgemm_kernel<<<dim3(DKV / BN,     T_SEQ / BM), 256>>>(x, Wk, K, T_SEQ, DKV,     D_MODEL);
    sgemm_kernel<<<dim3(DKV / BN,     T_SEQ / BM), 256>>>(x, Wv, V, T_SEQ, DKV,     D_MODEL);

    // Attention
    attn_kernel<<<dim3(T_SEQ / AQ, N_HQ), AQ, attn_smem>>>(Q, K, V, C);

    // Output projection
    sgemm_kernel<<<dim3(D_MODEL / BN, T_SEQ / BM), 256>>>(C, Wo, out, T_SEQ, D_MODEL, D_MODEL);
}